// round 5
// baseline (speedup 1.0000x reference)
#include <cuda_runtime.h>
#include <cuda_bf16.h>
#include <math.h>

// FFMCell: new_state = state * gamma(t) + x, gamma = exp((-|a| + i b) * t)
// T=4096, TRACE=64, CTX=64.
//
// R5: single fused kernel, grid = T blocks x 1024 threads. Each block covers
// one full t-tile (4096 elements = 1024 float4 groups), one group per thread
// (16 data regs -> 32 total, 2 blocks/SM = 100% occ). Factor amortization is
// maximal: 64 sincosf + 64 expf per 4096 elements (262k sincos total).
// Loads are front-batched before the factor prologue + single barrier, so
// DRAM streams through the MUFU phase; the co-resident block covers the
// barrier bubble.

__global__ void __launch_bounds__(1024, 2) ffm_tile_kernel(
    const float4* __restrict__ sre,
    const float4* __restrict__ sim,
    const float4* __restrict__ xre,
    const float4* __restrict__ xim,
    const float* __restrict__ a,
    const float* __restrict__ b,
    const int* __restrict__ ivec,
    const int* __restrict__ jvec,
    float* __restrict__ out,
    float* __restrict__ out_tail)
{
    const int t   = blockIdx.x;
    const int tid = threadIdx.x;

    __shared__ float  s_dec[64];
    __shared__ float2 s_cs[64];              // (cos, sin) per ctx

    // ---- Phase 0: front-batch this thread's 4 streaming loads -----------
    const long long g = (long long)t * 1024 + tid;   // float4-group index
    const float4 sr = __ldcs(&sre[g]);
    const float4 si = __ldcs(&sim[g]);
    const float4 xr = __ldcs(&xre[g]);
    const float4 xi = __ldcs(&xim[g]);

    // ---- Phase 1: per-tile factors (overlap with loads in flight) -------
    if (tid < 64) {
        const float tf = (float)__ldg(&jvec[t]);
        const float th = __ldg(&b[tid]) * tf;   // same fp32 product as ref
        float sn, cs;
        sincosf(th, &sn, &cs);
        s_cs[tid] = make_float2(cs, sn);
    } else if (tid < 128) {
        const float tf = (float)__ldg(&jvec[t]);
        s_dec[tid - 64] = expf(-fabsf(__ldg(&a[tid - 64])) * tf);
    } else if (tid == 128 && out_tail != nullptr) {
        out_tail[t] = (float)(__ldg(&jvec[t]) + __ldg(&ivec[t]));
    }
    __syncthreads();

    // ---- Phase 2: compute + store ----------------------------------------
    const int tr = tid >> 4;                  // trace row 0..63
    const int c2 = (tid & 15) << 1;           // float4 index into s_cs

    const float dec = s_dec[tr];
    const float4* s_cs4 = reinterpret_cast<const float4*>(s_cs);
    const float4 csA = s_cs4[c2];             // (cos0,sin0,cos1,sin1)
    const float4 csB = s_cs4[c2 + 1];         // (cos2,sin2,cos3,sin3)

    const float gr0 = dec * csA.x, gi0 = dec * csA.y;
    const float gr1 = dec * csA.z, gi1 = dec * csA.w;
    const float gr2 = dec * csB.x, gi2 = dec * csB.y;
    const float gr3 = dec * csB.z, gi3 = dec * csB.w;

    float4 o0, o1;
    o0.x = fmaf(sr.x, gr0, fmaf(-si.x, gi0, xr.x));
    o0.y = fmaf(sr.x, gi0, fmaf( si.x, gr0, xi.x));
    o0.z = fmaf(sr.y, gr1, fmaf(-si.y, gi1, xr.y));
    o0.w = fmaf(sr.y, gi1, fmaf( si.y, gr1, xi.y));
    o1.x = fmaf(sr.z, gr2, fmaf(-si.z, gi2, xr.z));
    o1.y = fmaf(sr.z, gi2, fmaf( si.z, gr2, xi.z));
    o1.z = fmaf(sr.w, gr3, fmaf(-si.w, gi3, xr.w));
    o1.w = fmaf(sr.w, gi3, fmaf( si.w, gr3, xi.w));

    float4* __restrict__ out4 = reinterpret_cast<float4*>(out);
    out4[2 * g]     = o0;
    out4[2 * g + 1] = o1;
}

extern "C" void kernel_launch(void* const* d_in, const int* in_sizes, int n_in,
                              void* d_out, int out_size)
{
    const float4* sre = (const float4*)d_in[0];
    const float4* sim = (const float4*)d_in[1];
    const float4* xre = (const float4*)d_in[2];
    const float4* xim = (const float4*)d_in[3];
    const float*  a   = (const float*)d_in[4];
    const float*  b   = (const float*)d_in[5];
    const int*    iv  = (const int*)d_in[6];
    const int*    jv  = (const int*)d_in[7];

    const int T = in_sizes[6];                      // 4096
    const long long N = (long long)in_sizes[0];     // T*TRACE*CTX

    float* out = (float*)d_out;
    float* out_tail = nullptr;
    if ((long long)out_size > 2LL * N) {
        out_tail = out + 2LL * N;
    }

    ffm_tile_kernel<<<T, 1024>>>(sre, sim, xre, xim, a, b, iv, jv,
                                 out, out_tail);
}

// round 6
// speedup vs baseline: 1.1145x; 1.1145x over previous
#include <cuda_runtime.h>
#include <cuda_bf16.h>
#include <math.h>

// FFMCell: new_state = state * gamma(t) + x, gamma = exp((-|a| + i b) * t)
// T=4096, TRACE=64, CTX=64.
//
// R6: two kernels with PDL overlap.
//   1) table_kernel: dec[t][tr]=exp(-|a|*t), cs[t][c]=(cos(b t), sin(b t))
//      into __device__ scratch; writes (j+i) tail; triggers dependent launch.
//   2) hot_kernel (PDL secondary): front-batches its 4 streaming LDG.128s,
//      THEN griddepcontrol.wait, then reads the table (L2-resident) and
//      stores. 32-bit index math, ~32 regs -> high occupancy, no barrier,
//      no MUFU in the hot path.

#define TMAX 4096
#define KDIM 64

__device__ float  g_dec[TMAX * KDIM];
__device__ float2 g_cs [TMAX * KDIM];

__global__ void __launch_bounds__(256) table_kernel(
    const float* __restrict__ a,
    const float* __restrict__ b,
    const int* __restrict__ iv,
    const int* __restrict__ jv,
    float* __restrict__ tail,
    int total)
{
    const int idx = blockIdx.x * blockDim.x + threadIdx.x;
    if (idx < total) {
        const int t = idx >> 6;
        const int k = idx & 63;

        const float tf = (float)__ldg(&jv[t]);

        g_dec[idx] = expf(-fabsf(__ldg(&a[k])) * tf);

        const float th = __ldg(&b[k]) * tf;   // same fp32 product as reference
        float sn, cs;
        sincosf(th, &sn, &cs);
        g_cs[idx] = make_float2(cs, sn);

        if (k == 0 && tail != nullptr) {
            tail[t] = (float)(__ldg(&jv[t]) + __ldg(&iv[t]));
        }
    }
    // Allow the dependent (hot) kernel's blocks to launch; its
    // griddepcontrol.wait still guarantees visibility of our stores.
    asm volatile("griddepcontrol.launch_dependents;");
}

__global__ void __launch_bounds__(256, 6) hot_kernel(
    const float4* __restrict__ sre,
    const float4* __restrict__ sim,
    const float4* __restrict__ xre,
    const float4* __restrict__ xim,
    float4* __restrict__ out4,
    int ngroups)
{
    const int g = blockIdx.x * 256 + threadIdx.x;
    if (g >= ngroups) {
        asm volatile("griddepcontrol.wait;" ::: "memory");
        return;
    }

    // ---- Phase 0: streaming loads, independent of the table --------------
    const float4 sr = __ldcs(&sre[g]);
    const float4 si = __ldcs(&sim[g]);
    const float4 xr = __ldcs(&xre[g]);
    const float4 xi = __ldcs(&xim[g]);

    // ---- Wait for table kernel completion (loads already in flight) ------
    asm volatile("griddepcontrol.wait;" ::: "memory");

    // ---- Table lookups (L2/L1 resident; dec reused 16x, cs lines 64x) ----
    const float dec = __ldg(&g_dec[g >> 4]);
    const float4* __restrict__ cs4 = reinterpret_cast<const float4*>(g_cs);
    const int ci = ((g >> 10) << 5) + ((g & 15) << 1);
    const float4 csA = __ldg(&cs4[ci]);       // (cos0, sin0, cos1, sin1)
    const float4 csB = __ldg(&cs4[ci + 1]);   // (cos2, sin2, cos3, sin3)

    const float gr0 = dec * csA.x, gi0 = dec * csA.y;
    const float gr1 = dec * csA.z, gi1 = dec * csA.w;
    const float gr2 = dec * csB.x, gi2 = dec * csB.y;
    const float gr3 = dec * csB.z, gi3 = dec * csB.w;

    float4 o0, o1;
    o0.x = fmaf(sr.x, gr0, fmaf(-si.x, gi0, xr.x));
    o0.y = fmaf(sr.x, gi0, fmaf( si.x, gr0, xi.x));
    o0.z = fmaf(sr.y, gr1, fmaf(-si.y, gi1, xr.y));
    o0.w = fmaf(sr.y, gi1, fmaf( si.y, gr1, xi.y));
    o1.x = fmaf(sr.z, gr2, fmaf(-si.z, gi2, xr.z));
    o1.y = fmaf(sr.z, gi2, fmaf( si.z, gr2, xi.z));
    o1.z = fmaf(sr.w, gr3, fmaf(-si.w, gi3, xr.w));
    o1.w = fmaf(sr.w, gi3, fmaf( si.w, gr3, xi.w));

    out4[2 * g]     = o0;
    out4[2 * g + 1] = o1;
}

extern "C" void kernel_launch(void* const* d_in, const int* in_sizes, int n_in,
                              void* d_out, int out_size)
{
    const float4* sre = (const float4*)d_in[0];
    const float4* sim = (const float4*)d_in[1];
    const float4* xre = (const float4*)d_in[2];
    const float4* xim = (const float4*)d_in[3];
    const float*  a   = (const float*)d_in[4];
    const float*  b   = (const float*)d_in[5];
    const int*    iv  = (const int*)d_in[6];
    const int*    jv  = (const int*)d_in[7];

    const int T = in_sizes[6];                      // 4096
    const long long N = (long long)in_sizes[0];     // T*TRACE*CTX

    float* out = (float*)d_out;
    float* out_tail = nullptr;
    if ((long long)out_size > 2LL * N) {
        out_tail = out + 2LL * N;
    }

    // 1) factor table (+ tail), primary
    int total = T * KDIM;
    if (total > TMAX * KDIM) total = TMAX * KDIM;
    table_kernel<<<(total + 255) / 256, 256>>>(a, b, iv, jv, out_tail, total);

    // 2) streaming hot kernel as PDL secondary: its blocks launch while the
    //    table kernel drains; each block front-batches loads before waiting.
    const int ngroups = (int)(N / 4);
    const int blocks = (ngroups + 255) / 256;

    cudaLaunchConfig_t cfg = {};
    cfg.gridDim  = dim3((unsigned)blocks, 1, 1);
    cfg.blockDim = dim3(256, 1, 1);
    cfg.dynamicSmemBytes = 0;
    cfg.stream = 0;   // same (legacy default) stream the other launch used
    cudaLaunchAttribute attrs[1];
    attrs[0].id = cudaLaunchAttributeProgrammaticStreamSerialization;
    attrs[0].val.programmaticStreamSerializationAllowed = 1;
    cfg.attrs = attrs;
    cfg.numAttrs = 1;

    cudaLaunchKernelEx(&cfg, hot_kernel,
                       sre, sim, xre, xim,
                       reinterpret_cast<float4*>(out), ngroups);
}

// round 7
// speedup vs baseline: 1.1541x; 1.0355x over previous
#include <cuda_runtime.h>
#include <cuda_bf16.h>
#include <math.h>

// FFMCell: new_state = state * gamma(t) + x, gamma = exp((-|a| + i b) * t)
// T=4096, TRACE=64, CTX=64.
//
// R7: single fused kernel, grid = T, 256 threads, 4 float4-groups/thread
// covering one t-tile. Software pipeline (depth 1): iter-0 loads are issued
// before the factor prologue + single barrier; inside the unrolled loop the
// next iteration's loads are issued before computing/storing the current
// one. Full factor amortization (64 sincos + 64 exp per 4096 elements).
// Per-thread cos/sin pair is loop-invariant and hoisted; only the decay
// value changes per iteration (LDS.32).

__global__ void __launch_bounds__(256, 4) ffm_pipe_kernel(
    const float4* __restrict__ sre,
    const float4* __restrict__ sim,
    const float4* __restrict__ xre,
    const float4* __restrict__ xim,
    const float* __restrict__ a,
    const float* __restrict__ b,
    const int* __restrict__ ivec,
    const int* __restrict__ jvec,
    float* __restrict__ out,
    float* __restrict__ out_tail)
{
    const int t   = blockIdx.x;
    const int tid = threadIdx.x;

    __shared__ float  s_dec[64];
    __shared__ float2 s_cs[64];             // (cos, sin) per ctx

    const int g0 = t * 1024 + tid;          // first float4-group (fits int32)

    // ---- Phase 0: iter-0 loads in flight before anything else ------------
    float4 sr = __ldcs(&sre[g0]);
    float4 si = __ldcs(&sim[g0]);
    float4 xr = __ldcs(&xre[g0]);
    float4 xi = __ldcs(&xim[g0]);

    // ---- Phase 1: per-tile factors ---------------------------------------
    if (tid < 64) {
        const float tf = (float)__ldg(&jvec[t]);
        const float th = __ldg(&b[tid]) * tf;   // same fp32 product as ref
        float sn, cs;
        sincosf(th, &sn, &cs);
        s_cs[tid] = make_float2(cs, sn);
    } else if (tid < 128) {
        const float tf = (float)__ldg(&jvec[t]);
        s_dec[tid - 64] = expf(-fabsf(__ldg(&a[tid - 64])) * tf);
    } else if (tid == 128 && out_tail != nullptr) {
        out_tail[t] = (float)(__ldg(&jvec[t]) + __ldg(&ivec[t]));
    }
    __syncthreads();

    // Loop-invariant per-thread cos/sin (this thread's 4 ctx columns).
    const float4* s_cs4 = reinterpret_cast<const float4*>(s_cs);
    const int cbase = (tid & 15) << 1;
    const float4 csA = s_cs4[cbase];        // (cos0,sin0,cos1,sin1)
    const float4 csB = s_cs4[cbase + 1];    // (cos2,sin2,cos3,sin3)

    float4* __restrict__ out4 = reinterpret_cast<float4*>(out);
    const int tr0 = tid >> 4;               // local trace row of iter 0

    // ---- Phase 2: pipelined compute/store over 4 iterations --------------
    #pragma unroll
    for (int it = 0; it < 4; ++it) {
        // Prefetch next iteration's tiles (kept in regs across compute).
        float4 nsr, nsi, nxr, nxi;
        if (it < 3) {
            const int gn = g0 + (it + 1) * 256;
            nsr = __ldcs(&sre[gn]);
            nsi = __ldcs(&sim[gn]);
            nxr = __ldcs(&xre[gn]);
            nxi = __ldcs(&xim[gn]);
        }

        const float dec = s_dec[it * 16 + tr0];

        const float gr0 = dec * csA.x, gi0 = dec * csA.y;
        const float gr1 = dec * csA.z, gi1 = dec * csA.w;
        const float gr2 = dec * csB.x, gi2 = dec * csB.y;
        const float gr3 = dec * csB.z, gi3 = dec * csB.w;

        float4 o0, o1;
        o0.x = fmaf(sr.x, gr0, fmaf(-si.x, gi0, xr.x));
        o0.y = fmaf(sr.x, gi0, fmaf( si.x, gr0, xi.x));
        o0.z = fmaf(sr.y, gr1, fmaf(-si.y, gi1, xr.y));
        o0.w = fmaf(sr.y, gi1, fmaf( si.y, gr1, xi.y));
        o1.x = fmaf(sr.z, gr2, fmaf(-si.z, gi2, xr.z));
        o1.y = fmaf(sr.z, gi2, fmaf( si.z, gr2, xi.z));
        o1.z = fmaf(sr.w, gr3, fmaf(-si.w, gi3, xr.w));
        o1.w = fmaf(sr.w, gi3, fmaf( si.w, gr3, xi.w));

        const int g = g0 + it * 256;
        out4[2 * g]     = o0;
        out4[2 * g + 1] = o1;

        sr = nsr; si = nsi; xr = nxr; xi = nxi;
    }
}

extern "C" void kernel_launch(void* const* d_in, const int* in_sizes, int n_in,
                              void* d_out, int out_size)
{
    const float4* sre = (const float4*)d_in[0];
    const float4* sim = (const float4*)d_in[1];
    const float4* xre = (const float4*)d_in[2];
    const float4* xim = (const float4*)d_in[3];
    const float*  a   = (const float*)d_in[4];
    const float*  b   = (const float*)d_in[5];
    const int*    iv  = (const int*)d_in[6];
    const int*    jv  = (const int*)d_in[7];

    const int T = in_sizes[6];                      // 4096
    const long long N = (long long)in_sizes[0];     // T*TRACE*CTX

    float* out = (float*)d_out;
    float* out_tail = nullptr;
    if ((long long)out_size > 2LL * N) {
        out_tail = out + 2LL * N;
    }

    ffm_pipe_kernel<<<T, 256>>>(sre, sim, xre, xim, a, b, iv, jv,
                                out, out_tail);
}